// round 3
// baseline (speedup 1.0000x reference)
#include <cuda_runtime.h>
#include <math.h>

// Problem constants (derived at runtime, buffers sized for max)
#define F 128
#define MAXN 50048
#define MAXE 800064

// Scratch (allocation-free rule: __device__ globals)
__device__ __align__(16) float g_W[F * F];            // evolved weight
__device__ __align__(16) float g_xw[(size_t)MAXN * F]; // x @ W
__device__ __align__(16) float g_h[(size_t)MAXN * F];  // aggregated features
__device__ float g_dinv[MAXN];                          // deg -> rsqrt(deg)

// ---------------------------------------------------------------------------
// 1) GRU weight evolution: W = gru(W0)
//    gi = W0 @ W_ih^T + b_ih ; gh = W0 @ W_hh^T + b_hh
//    One thread per W[i][j]: 6 dot products of K=128 (all operands L2-resident).
// ---------------------------------------------------------------------------
__global__ void k_gru(const float* __restrict__ W0,
                      const float* __restrict__ Wih,
                      const float* __restrict__ Whh,
                      const float* __restrict__ bih,
                      const float* __restrict__ bhh) {
    int t = blockIdx.x * blockDim.x + threadIdx.x;
    if (t >= F * F) return;
    int i = t >> 7;
    int j = t & 127;

    const float* w0r = W0 + i * F;
    const float* a_r = Wih + (size_t)j * F;
    const float* a_z = Wih + (size_t)(j + F) * F;
    const float* a_n = Wih + (size_t)(j + 2 * F) * F;
    const float* h_r = Whh + (size_t)j * F;
    const float* h_z = Whh + (size_t)(j + F) * F;
    const float* h_n = Whh + (size_t)(j + 2 * F) * F;

    float ir = 0.f, iz = 0.f, in_ = 0.f, hr = 0.f, hz = 0.f, hn = 0.f;
#pragma unroll 8
    for (int k = 0; k < F; k++) {
        float w0 = __ldg(w0r + k);
        ir += w0 * __ldg(a_r + k);
        iz += w0 * __ldg(a_z + k);
        in_ += w0 * __ldg(a_n + k);
        hr += w0 * __ldg(h_r + k);
        hz += w0 * __ldg(h_z + k);
        hn += w0 * __ldg(h_n + k);
    }
    ir += __ldg(bih + j);
    iz += __ldg(bih + j + F);
    in_ += __ldg(bih + j + 2 * F);
    hr += __ldg(bhh + j);
    hz += __ldg(bhh + j + F);
    hn += __ldg(bhh + j + 2 * F);

    float r = 1.f / (1.f + expf(-(ir + hr)));
    float z = 1.f / (1.f + expf(-(iz + hz)));
    float n = tanhf(in_ + r * hn);
    g_W[t] = (1.f - z) * n + z * __ldg(W0 + t);
}

// ---------------------------------------------------------------------------
// 2) Degree: init to 1.0 (self-loop weight), scatter edge weights, then rsqrt.
// ---------------------------------------------------------------------------
__global__ void k_deg_init(int N) {
    int t = blockIdx.x * blockDim.x + threadIdx.x;
    if (t < N) g_dinv[t] = 1.0f;  // g_dinv temporarily holds deg
}

__global__ void k_deg_scatter(const int* __restrict__ dst,
                              const float* __restrict__ ew, int E) {
    int t = blockIdx.x * blockDim.x + threadIdx.x;
    if (t < E) atomicAdd(&g_dinv[__ldg(dst + t)], __ldg(ew + t));
}

__global__ void k_dinv(int N) {
    int t = blockIdx.x * blockDim.x + threadIdx.x;
    if (t < N) {
        float d = g_dinv[t];
        g_dinv[t] = (d > 0.f) ? rsqrtf(d) : 0.f;
    }
}

// ---------------------------------------------------------------------------
// 3) GEMM: g_xw = x @ g_W   (N x 128) @ (128 x 128), fp32.
//    Block = 64 rows, 256 threads. thread: row = tid&63, colgroup = tid>>6
//    (32 cols each). W k-row loads are warp-broadcast LDS.128; x reads are
//    conflict-free (stride-33 padding).
// ---------------------------------------------------------------------------
__global__ void k_gemm(const float* __restrict__ x, int N) {
    __shared__ float Ws[32 * F];      // 16 KB: K-tile of W
    __shared__ float Xs[64 * 33];     // 8.25 KB: x tile, padded
    int tid = threadIdx.x;
    int row = tid & 63;
    int colg = tid >> 6;              // 0..3
    int row0 = blockIdx.x * 64;

    float acc[32];
#pragma unroll
    for (int c = 0; c < 32; c++) acc[c] = 0.f;

    for (int kt = 0; kt < 4; kt++) {
        __syncthreads();
        // load W K-tile: rows kt*32..+32, 4096 floats = 1024 float4
#pragma unroll
        for (int i = 0; i < 4; i++) {
            int idx = tid + i * 256;
            reinterpret_cast<float4*>(Ws)[idx] =
                reinterpret_cast<const float4*>(g_W + kt * 32 * F)[idx];
        }
        // load x tile: 64 rows x 32 k, coalesced scalar
#pragma unroll
        for (int i = 0; i < 8; i++) {
            int e = tid + i * 256;            // 0..2047
            int r = e >> 5, kk = e & 31;
            float v = (row0 + r < N) ? __ldg(x + (size_t)(row0 + r) * F + kt * 32 + kk) : 0.f;
            Xs[r * 33 + kk] = v;
        }
        __syncthreads();
#pragma unroll
        for (int k = 0; k < 32; k++) {
            float xv = Xs[row * 33 + k];
            const float4* wr = reinterpret_cast<const float4*>(Ws + k * F + colg * 32);
#pragma unroll
            for (int c8 = 0; c8 < 8; c8++) {
                float4 w4 = wr[c8];
                acc[c8 * 4 + 0] += xv * w4.x;
                acc[c8 * 4 + 1] += xv * w4.y;
                acc[c8 * 4 + 2] += xv * w4.z;
                acc[c8 * 4 + 3] += xv * w4.w;
            }
        }
    }
    if (row0 + row < N) {
        float4* o4 = reinterpret_cast<float4*>(g_xw + (size_t)(row0 + row) * F + colg * 32);
#pragma unroll
        for (int c8 = 0; c8 < 8; c8++)
            o4[c8] = make_float4(acc[c8 * 4], acc[c8 * 4 + 1], acc[c8 * 4 + 2], acc[c8 * 4 + 3]);
    }
}

// ---------------------------------------------------------------------------
// 4a) h init with self-loop contribution: h[i] = dinv[i]^2 * xw[i]
//     (deterministic init; avoids N extra atomic rows)
// ---------------------------------------------------------------------------
__global__ void k_hinit(int N) {
    int t = blockIdx.x * blockDim.x + threadIdx.x;  // one float4 per thread
    if (t >= N * 32) return;
    int node = t >> 5;
    float di = g_dinv[node];
    float c = di * di;
    float4 v = reinterpret_cast<const float4*>(g_xw)[t];
    reinterpret_cast<float4*>(g_h)[t] = make_float4(c * v.x, c * v.y, c * v.z, c * v.w);
}

// ---------------------------------------------------------------------------
// 4b) Edge scatter: warp per edge. Gather xw[src] (L2-resident), scale by
//     norm, reduce into h[dst] with red.global.add.v4.f32 (16B per lane).
// ---------------------------------------------------------------------------
__global__ void k_scatter(const int* __restrict__ src,
                          const int* __restrict__ dst,
                          const float* __restrict__ ew, int E) {
    int gw = (blockIdx.x * blockDim.x + threadIdx.x) >> 5;
    int lane = threadIdx.x & 31;
    if (gw >= E) return;
    int s = __ldg(src + gw);
    int d = __ldg(dst + gw);
    float coef = g_dinv[s] * __ldg(ew + gw) * g_dinv[d];
    float4 v = reinterpret_cast<const float4*>(g_xw + (size_t)s * F)[lane];
    float* hp = g_h + (size_t)d * F + lane * 4;
    asm volatile(
        "red.global.add.v4.f32 [%0], {%1, %2, %3, %4};"
        :: "l"(hp), "f"(coef * v.x), "f"(coef * v.y), "f"(coef * v.z), "f"(coef * v.w)
        : "memory");
}

// ---------------------------------------------------------------------------
// 5) Output: out[i] = sum_c tanh(h[i][c]) * w_lin[c] + b_lin. Warp per node.
// ---------------------------------------------------------------------------
__global__ void k_out(const float* __restrict__ wlin,
                      const float* __restrict__ blin,
                      float* __restrict__ out, int N) {
    int gw = (blockIdx.x * blockDim.x + threadIdx.x) >> 5;
    int lane = threadIdx.x & 31;
    if (gw >= N) return;
    float4 hv = reinterpret_cast<const float4*>(g_h + (size_t)gw * F)[lane];
    float4 wv = reinterpret_cast<const float4*>(wlin)[lane];
    float sum = tanhf(hv.x) * wv.x + tanhf(hv.y) * wv.y +
                tanhf(hv.z) * wv.z + tanhf(hv.w) * wv.w;
#pragma unroll
    for (int o = 16; o; o >>= 1) sum += __shfl_xor_sync(0xffffffffu, sum, o);
    if (lane == 0) out[gw] = sum + __ldg(blin);
}

// ---------------------------------------------------------------------------
extern "C" void kernel_launch(void* const* d_in, const int* in_sizes, int n_in,
                              void* d_out, int out_size) {
    const float* x    = (const float*)d_in[0];
    const int*   ei   = (const int*)d_in[1];
    const float* ew   = (const float*)d_in[2];
    const float* W0   = (const float*)d_in[3];
    const float* Wih  = (const float*)d_in[4];
    const float* Whh  = (const float*)d_in[5];
    const float* bih  = (const float*)d_in[6];
    const float* bhh  = (const float*)d_in[7];
    const float* wlin = (const float*)d_in[8];
    const float* blin = (const float*)d_in[9];
    float* out = (float*)d_out;

    int N = in_sizes[0] / F;
    int E = in_sizes[2];
    const int* src = ei;
    const int* dst = ei + E;

    k_gru<<<(F * F + 255) / 256, 256>>>(W0, Wih, Whh, bih, bhh);
    k_deg_init<<<(N + 255) / 256, 256>>>(N);
    k_deg_scatter<<<(E + 255) / 256, 256>>>(dst, ew, E);
    k_dinv<<<(N + 255) / 256, 256>>>(N);
    k_gemm<<<(N + 63) / 64, 256>>>(x, N);
    k_hinit<<<(N * 32 + 255) / 256, 256>>>(N);
    k_scatter<<<(E + 7) / 8, 256>>>(src, dst, ew, E);  // 8 warps/block, warp/edge
    k_out<<<(N + 7) / 8, 256>>>(wlin, blin, out, N);
}

// round 5
// speedup vs baseline: 1.1878x; 1.1878x over previous
#include <cuda_runtime.h>
#include <math.h>

#define F 128
#define MAXN 50048
#define MAXE 800064

// Scratch (__device__ globals; no allocation allowed)
__device__ __align__(16) float g_W[F * F];              // evolved weight
__device__ __align__(16) float g_xw[(size_t)MAXN * F];  // x @ W
__device__ float g_dinv[MAXN];                          // deg -> rsqrt(deg)
__device__ int   g_cnt[MAXN];                           // per-dst edge count
__device__ int   g_off[MAXN];                           // exclusive scan of counts
__device__ int   g_cur[MAXN];                           // placement cursors
__device__ int   g_part[512];                           // scan partials
__device__ __align__(16) int   g_ssrc[MAXE];            // dst-sorted src ids
__device__ __align__(16) float g_scoef[MAXE];           // dst-sorted norm coefs

// ---------------------------------------------------------------------------
// 1) GRU weight evolution: W = gru(W0)
// ---------------------------------------------------------------------------
__global__ void k_gru(const float* __restrict__ W0,
                      const float* __restrict__ Wih,
                      const float* __restrict__ Whh,
                      const float* __restrict__ bih,
                      const float* __restrict__ bhh) {
    int t = blockIdx.x * blockDim.x + threadIdx.x;
    if (t >= F * F) return;
    int i = t >> 7;
    int j = t & 127;

    const float* w0r = W0 + i * F;
    const float* a_r = Wih + (size_t)j * F;
    const float* a_z = Wih + (size_t)(j + F) * F;
    const float* a_n = Wih + (size_t)(j + 2 * F) * F;
    const float* h_r = Whh + (size_t)j * F;
    const float* h_z = Whh + (size_t)(j + F) * F;
    const float* h_n = Whh + (size_t)(j + 2 * F) * F;

    float ir = 0.f, iz = 0.f, in_ = 0.f, hr = 0.f, hz = 0.f, hn = 0.f;
#pragma unroll 8
    for (int k = 0; k < F; k++) {
        float w0 = __ldg(w0r + k);
        ir += w0 * __ldg(a_r + k);
        iz += w0 * __ldg(a_z + k);
        in_ += w0 * __ldg(a_n + k);
        hr += w0 * __ldg(h_r + k);
        hz += w0 * __ldg(h_z + k);
        hn += w0 * __ldg(h_n + k);
    }
    ir += __ldg(bih + j);
    iz += __ldg(bih + j + F);
    in_ += __ldg(bih + j + 2 * F);
    hr += __ldg(bhh + j);
    hz += __ldg(bhh + j + F);
    hn += __ldg(bhh + j + 2 * F);

    float r = 1.f / (1.f + expf(-(ir + hr)));
    float z = 1.f / (1.f + expf(-(iz + hz)));
    float n = tanhf(in_ + r * hn);
    g_W[t] = (1.f - z) * n + z * __ldg(W0 + t);
}

// ---------------------------------------------------------------------------
// 2) zero counts, deg=1 (self-loop weight)
// ---------------------------------------------------------------------------
__global__ void k_zero(int N) {
    int t = blockIdx.x * blockDim.x + threadIdx.x;
    if (t < N) { g_cnt[t] = 0; g_dinv[t] = 1.0f; }
}

// 3) histogram: per-dst edge count (int) + weighted degree (float)
__global__ void k_hist(const int* __restrict__ dst,
                       const float* __restrict__ ew, int E) {
    int t = blockIdx.x * blockDim.x + threadIdx.x;
    if (t < E) {
        int d = __ldg(dst + t);
        atomicAdd(&g_cnt[d], 1);
        atomicAdd(&g_dinv[d], __ldg(ew + t));
    }
}

__global__ void k_dinv(int N) {
    int t = blockIdx.x * blockDim.x + threadIdx.x;
    if (t < N) {
        float d = g_dinv[t];
        g_dinv[t] = (d > 0.f) ? rsqrtf(d) : 0.f;
    }
}

// ---------------------------------------------------------------------------
// 4) exclusive scan of g_cnt -> g_off (3 kernels; N <= 50176 = 196 blocks)
// ---------------------------------------------------------------------------
__global__ void k_scan1(int N) {
    __shared__ int sh[256];
    int tid = threadIdx.x;
    int gid = blockIdx.x * 256 + tid;
    int v = (gid < N) ? g_cnt[gid] : 0;
    sh[tid] = v;
    __syncthreads();
#pragma unroll
    for (int o = 1; o < 256; o <<= 1) {
        int t = (tid >= o) ? sh[tid - o] : 0;
        __syncthreads();
        sh[tid] += t;
        __syncthreads();
    }
    if (gid < N) g_off[gid] = sh[tid] - v;      // exclusive within block
    if (tid == 255) g_part[blockIdx.x] = sh[255];
}

__global__ void k_scan2(int nb) {
    __shared__ int sh[256];
    int tid = threadIdx.x;
    int v = (tid < nb) ? g_part[tid] : 0;
    sh[tid] = v;
    __syncthreads();
#pragma unroll
    for (int o = 1; o < 256; o <<= 1) {
        int t = (tid >= o) ? sh[tid - o] : 0;
        __syncthreads();
        sh[tid] += t;
        __syncthreads();
    }
    if (tid < nb) g_part[tid] = sh[tid] - v;    // exclusive
}

__global__ void k_scan3(int N) {
    int gid = blockIdx.x * 256 + threadIdx.x;
    if (gid < N) {
        int o = g_off[gid] + g_part[blockIdx.x];
        g_off[gid] = o;
        g_cur[gid] = o;
    }
}

// ---------------------------------------------------------------------------
// 5) placement: counting-sort edges by dst; precompute norm coefficient
// ---------------------------------------------------------------------------
__global__ void k_place(const int* __restrict__ src,
                        const int* __restrict__ dst,
                        const float* __restrict__ ew, int E) {
    int t = blockIdx.x * blockDim.x + threadIdx.x;
    if (t >= E) return;
    int s = __ldg(src + t);
    int d = __ldg(dst + t);
    float c = g_dinv[s] * __ldg(ew + t) * g_dinv[d];
    int p = atomicAdd(&g_cur[d], 1);
    g_ssrc[p] = s;
    g_scoef[p] = c;
}

// ---------------------------------------------------------------------------
// 6) GEMM: g_xw = x @ g_W   (unchanged from R0; passed)
// ---------------------------------------------------------------------------
__global__ void k_gemm(const float* __restrict__ x, int N) {
    __shared__ float Ws[32 * F];
    __shared__ float Xs[64 * 33];
    int tid = threadIdx.x;
    int row = tid & 63;
    int colg = tid >> 6;
    int row0 = blockIdx.x * 64;

    float acc[32];
#pragma unroll
    for (int c = 0; c < 32; c++) acc[c] = 0.f;

    for (int kt = 0; kt < 4; kt++) {
        __syncthreads();
#pragma unroll
        for (int i = 0; i < 4; i++) {
            int idx = tid + i * 256;
            reinterpret_cast<float4*>(Ws)[idx] =
                reinterpret_cast<const float4*>(g_W + kt * 32 * F)[idx];
        }
#pragma unroll
        for (int i = 0; i < 8; i++) {
            int e = tid + i * 256;
            int r = e >> 5, kk = e & 31;
            float v = (row0 + r < N) ? __ldg(x + (size_t)(row0 + r) * F + kt * 32 + kk) : 0.f;
            Xs[r * 33 + kk] = v;
        }
        __syncthreads();
#pragma unroll
        for (int k = 0; k < 32; k++) {
            float xv = Xs[row * 33 + k];
            const float4* wr = reinterpret_cast<const float4*>(Ws + k * F + colg * 32);
#pragma unroll
            for (int c8 = 0; c8 < 8; c8++) {
                float4 w4 = wr[c8];
                acc[c8 * 4 + 0] += xv * w4.x;
                acc[c8 * 4 + 1] += xv * w4.y;
                acc[c8 * 4 + 2] += xv * w4.z;
                acc[c8 * 4 + 3] += xv * w4.w;
            }
        }
    }
    if (row0 + row < N) {
        float4* o4 = reinterpret_cast<float4*>(g_xw + (size_t)(row0 + row) * F + colg * 32);
#pragma unroll
        for (int c8 = 0; c8 < 8; c8++)
            o4[c8] = make_float4(acc[c8 * 4], acc[c8 * 4 + 1], acc[c8 * 4 + 2], acc[c8 * 4 + 3]);
    }
}

// ---------------------------------------------------------------------------
// 7) Fused aggregation + tanh + linear output. Warp per dst node.
//    acc = dinv^2 * xw[node]  (self-loop), then register-resident segmented
//    reduction over the dst-sorted edge list (NO float atomics, no h array),
//    then out[node] = sum_c tanh(acc_c) * wlin_c + blin.
// ---------------------------------------------------------------------------
__global__ void k_agg_out(const float* __restrict__ wlin,
                          const float* __restrict__ blin,
                          float* __restrict__ out, int N) {
    int node = (blockIdx.x * blockDim.x + threadIdx.x) >> 5;
    int lane = threadIdx.x & 31;
    if (node >= N) return;

    float di = g_dinv[node];
    float4 v0 = reinterpret_cast<const float4*>(g_xw + (size_t)node * F)[lane];
    float c0 = di * di;
    float ax = c0 * v0.x, ay = c0 * v0.y, az = c0 * v0.z, aw = c0 * v0.w;

    int beg = g_off[node];
    int cnt = g_cnt[node];

    for (int base = 0; base < cnt; base += 32) {
        int rem = cnt - base;
        int n = rem < 32 ? rem : 32;
        int s = 0;
        float c = 0.f;
        if (lane < n) {
            s = __ldg(g_ssrc + beg + base + lane);
            c = __ldg(g_scoef + beg + base + lane);
        }
        int j = 0;
        // unrolled-by-2 gather for MLP
        for (; j + 2 <= n; j += 2) {
            int s0 = __shfl_sync(0xffffffffu, s, j);
            int s1 = __shfl_sync(0xffffffffu, s, j + 1);
            float cc0 = __shfl_sync(0xffffffffu, c, j);
            float cc1 = __shfl_sync(0xffffffffu, c, j + 1);
            float4 a = reinterpret_cast<const float4*>(g_xw + (size_t)s0 * F)[lane];
            float4 b = reinterpret_cast<const float4*>(g_xw + (size_t)s1 * F)[lane];
            ax += cc0 * a.x + cc1 * b.x;
            ay += cc0 * a.y + cc1 * b.y;
            az += cc0 * a.z + cc1 * b.z;
            aw += cc0 * a.w + cc1 * b.w;
        }
        if (j < n) {
            int s0 = __shfl_sync(0xffffffffu, s, j);
            float cc0 = __shfl_sync(0xffffffffu, c, j);
            float4 a = reinterpret_cast<const float4*>(g_xw + (size_t)s0 * F)[lane];
            ax += cc0 * a.x;
            ay += cc0 * a.y;
            az += cc0 * a.z;
            aw += cc0 * a.w;
        }
    }

    float4 wv = reinterpret_cast<const float4*>(wlin)[lane];
    float sum = tanhf(ax) * wv.x + tanhf(ay) * wv.y +
                tanhf(az) * wv.z + tanhf(aw) * wv.w;
#pragma unroll
    for (int o = 16; o; o >>= 1) sum += __shfl_xor_sync(0xffffffffu, sum, o);
    if (lane == 0) out[node] = sum + __ldg(blin);
}

// ---------------------------------------------------------------------------
extern "C" void kernel_launch(void* const* d_in, const int* in_sizes, int n_in,
                              void* d_out, int out_size) {
    const float* x    = (const float*)d_in[0];
    const int*   ei   = (const int*)d_in[1];
    const float* ew   = (const float*)d_in[2];
    const float* W0   = (const float*)d_in[3];
    const float* Wih  = (const float*)d_in[4];
    const float* Whh  = (const float*)d_in[5];
    const float* bih  = (const float*)d_in[6];
    const float* bhh  = (const float*)d_in[7];
    const float* wlin = (const float*)d_in[8];
    const float* blin = (const float*)d_in[9];
    float* out = (float*)d_out;

    int N = in_sizes[0] / F;
    int E = in_sizes[2];
    const int* src = ei;
    const int* dst = ei + E;
    int nb = (N + 255) / 256;   // scan blocks (196 for N=50000, <=256 required)

    k_gru<<<(F * F + 255) / 256, 256>>>(W0, Wih, Whh, bih, bhh);
    k_zero<<<nb, 256>>>(N);
    k_hist<<<(E + 255) / 256, 256>>>(dst, ew, E);
    k_dinv<<<nb, 256>>>(N);
    k_scan1<<<nb, 256>>>(N);
    k_scan2<<<1, 256>>>(nb);
    k_scan3<<<nb, 256>>>(N);
    k_place<<<(E + 255) / 256, 256>>>(src, dst, ew, E);
    k_gemm<<<(N + 63) / 64, 256>>>(x, N);
    k_agg_out<<<(N + 7) / 8, 256>>>(wlin, blin, out, N);
}

// round 7
// speedup vs baseline: 1.4971x; 1.2604x over previous
#include <cuda_runtime.h>
#include <math.h>
#include <stdint.h>

#define F 128
#define MAXN 50048
#define MAXE 800064

// Scratch (__device__ globals; no allocation allowed)
__device__ __align__(16) float g_W[F * F];              // evolved weight
__device__ __align__(16) float g_xw[(size_t)MAXN * F];  // x @ W
__device__ float g_dinv[MAXN];                          // deg -> rsqrt(deg)
__device__ int   g_cnt[MAXN];                           // per-dst edge count
__device__ int   g_off[MAXN];                           // exclusive scan
__device__ int   g_cur[MAXN];                           // placement cursors
__device__ int   g_part[512];                           // scan partials
__device__ __align__(16) int2 g_edge[MAXE];             // dst-sorted (src, coef-bits)

__device__ __forceinline__ uint32_t f2tf32(float f) {
    uint32_t u;
    asm("cvt.rna.tf32.f32 %0, %1;" : "=r"(u) : "f"(f));
    return u;
}

// ---------------------------------------------------------------------------
// 1) GRU weight evolution fused with cnt/deg init (threads beyond F*F zero).
// ---------------------------------------------------------------------------
__global__ void k_gru_zero(const float* __restrict__ W0,
                           const float* __restrict__ Wih,
                           const float* __restrict__ Whh,
                           const float* __restrict__ bih,
                           const float* __restrict__ bhh, int N) {
    int t = blockIdx.x * blockDim.x + threadIdx.x;
    if (t < N) { g_cnt[t] = 0; g_dinv[t] = 1.0f; }  // self-loop weight
    if (t >= F * F) return;
    int i = t >> 7;
    int j = t & 127;

    const float* w0r = W0 + i * F;
    const float* a_r = Wih + (size_t)j * F;
    const float* a_z = Wih + (size_t)(j + F) * F;
    const float* a_n = Wih + (size_t)(j + 2 * F) * F;
    const float* h_r = Whh + (size_t)j * F;
    const float* h_z = Whh + (size_t)(j + F) * F;
    const float* h_n = Whh + (size_t)(j + 2 * F) * F;

    float ir = 0.f, iz = 0.f, in_ = 0.f, hr = 0.f, hz = 0.f, hn = 0.f;
#pragma unroll 8
    for (int k = 0; k < F; k++) {
        float w0 = __ldg(w0r + k);
        ir += w0 * __ldg(a_r + k);
        iz += w0 * __ldg(a_z + k);
        in_ += w0 * __ldg(a_n + k);
        hr += w0 * __ldg(h_r + k);
        hz += w0 * __ldg(h_z + k);
        hn += w0 * __ldg(h_n + k);
    }
    ir += __ldg(bih + j);
    iz += __ldg(bih + j + F);
    in_ += __ldg(bih + j + 2 * F);
    hr += __ldg(bhh + j);
    hz += __ldg(bhh + j + F);
    hn += __ldg(bhh + j + 2 * F);

    float r = 1.f / (1.f + expf(-(ir + hr)));
    float z = 1.f / (1.f + expf(-(iz + hz)));
    float n = tanhf(in_ + r * hn);
    g_W[t] = (1.f - z) * n + z * __ldg(W0 + t);
}

// 2) histogram: per-dst edge count (int) + weighted degree (float)
__global__ void k_hist(const int* __restrict__ dst,
                       const float* __restrict__ ew, int E) {
    int t = blockIdx.x * blockDim.x + threadIdx.x;
    if (t < E) {
        int d = __ldg(dst + t);
        atomicAdd(&g_cnt[d], 1);
        atomicAdd(&g_dinv[d], __ldg(ew + t));
    }
}

// ---------------------------------------------------------------------------
// 3) scan (block-local) fused with dinv finalize
// ---------------------------------------------------------------------------
__global__ void k_scan1_dinv(int N) {
    __shared__ int sh[256];
    int tid = threadIdx.x;
    int gid = blockIdx.x * 256 + tid;
    if (gid < N) {                      // finalize dinv (hist is done)
        float d = g_dinv[gid];
        g_dinv[gid] = (d > 0.f) ? rsqrtf(d) : 0.f;
    }
    int v = (gid < N) ? g_cnt[gid] : 0;
    sh[tid] = v;
    __syncthreads();
#pragma unroll
    for (int o = 1; o < 256; o <<= 1) {
        int t = (tid >= o) ? sh[tid - o] : 0;
        __syncthreads();
        sh[tid] += t;
        __syncthreads();
    }
    if (gid < N) g_off[gid] = sh[tid] - v;
    if (tid == 255) g_part[blockIdx.x] = sh[255];
}

__global__ void k_scan2(int nb) {
    __shared__ int sh[256];
    int tid = threadIdx.x;
    int v = (tid < nb) ? g_part[tid] : 0;
    sh[tid] = v;
    __syncthreads();
#pragma unroll
    for (int o = 1; o < 256; o <<= 1) {
        int t = (tid >= o) ? sh[tid - o] : 0;
        __syncthreads();
        sh[tid] += t;
        __syncthreads();
    }
    if (tid < nb) g_part[tid] = sh[tid] - v;
}

__global__ void k_scan3(int N) {
    int gid = blockIdx.x * 256 + threadIdx.x;
    if (gid < N) {
        int o = g_off[gid] + g_part[blockIdx.x];
        g_off[gid] = o;
        g_cur[gid] = o;
    }
}

// ---------------------------------------------------------------------------
// 4) placement: counting-sort by dst, packed (src, coef) in one 8B store
// ---------------------------------------------------------------------------
__global__ void k_place(const int* __restrict__ src,
                        const int* __restrict__ dst,
                        const float* __restrict__ ew, int E) {
    int t = blockIdx.x * blockDim.x + threadIdx.x;
    if (t >= E) return;
    int s = __ldg(src + t);
    int d = __ldg(dst + t);
    float c = g_dinv[s] * __ldg(ew + t) * g_dinv[d];
    int p = atomicAdd(&g_cur[d], 1);
    g_edge[p] = make_int2(s, __float_as_int(c));
}

// ---------------------------------------------------------------------------
// 5) GEMM via tensor cores: g_xw = x @ g_W, tf32 mma.sync.m16n8k8, fp32 accum.
//    Block = 128 rows x 128 cols, 256 threads (8 warps); warp w owns rows
//    [w*16, w*16+16) x all 128 cols (16 n8 tiles). K in 4 tiles of 32.
//    Xs padded to 36 floats/row, Ws chunk padded to 136 floats/row ->
//    conflict-free fragment LDS. x and W rounded to tf32 once in smem.
// ---------------------------------------------------------------------------
__global__ void __launch_bounds__(256) k_gemm_tc(const float* __restrict__ x, int N) {
    __shared__ float Xs[128 * 36];   // [row][k] 18.4KB
    __shared__ float Ws[32 * 136];   // [k][n]  17.4KB (one 32-k chunk)
    int tid = threadIdx.x;
    int warp = tid >> 5, lane = tid & 31;
    int row0 = blockIdx.x * 128;
    int gid = lane >> 2;             // group id 0..7
    int tig = lane & 3;              // thread in group 0..3

    float acc[16][4];
#pragma unroll
    for (int nt = 0; nt < 16; nt++)
#pragma unroll
        for (int c = 0; c < 4; c++) acc[nt][c] = 0.f;

    for (int kt = 0; kt < 4; kt++) {
        __syncthreads();
        // load x tile: rows row0..+128, cols kt*32..+32 (tf32-rounded)
#pragma unroll
        for (int i = 0; i < 4; i++) {
            int e = tid + i * 256;           // 0..1023 float4s
            int r = e >> 3, kg = e & 7;
            float4 v = make_float4(0.f, 0.f, 0.f, 0.f);
            if (row0 + r < N)
                v = __ldg(reinterpret_cast<const float4*>(x + (size_t)(row0 + r) * F + kt * 32) + kg);
            v.x = __uint_as_float(f2tf32(v.x));
            v.y = __uint_as_float(f2tf32(v.y));
            v.z = __uint_as_float(f2tf32(v.z));
            v.w = __uint_as_float(f2tf32(v.w));
            reinterpret_cast<float4*>(Xs)[r * 9 + kg] = v;   // 36 floats = 9 float4
        }
        // load W chunk: k rows kt*32..+32, all 128 cols (tf32-rounded)
#pragma unroll
        for (int i = 0; i < 4; i++) {
            int e = tid + i * 256;           // 0..1023 float4s
            int r = e >> 5, cg = e & 31;
            float4 v = reinterpret_cast<const float4*>(g_W + (size_t)(kt * 32 + r) * F)[cg];
            v.x = __uint_as_float(f2tf32(v.x));
            v.y = __uint_as_float(f2tf32(v.y));
            v.z = __uint_as_float(f2tf32(v.z));
            v.w = __uint_as_float(f2tf32(v.w));
            reinterpret_cast<float4*>(Ws)[r * 34 + cg] = v;  // 136 floats = 34 float4
        }
        __syncthreads();

#pragma unroll
        for (int ks = 0; ks < 4; ks++) {
            int k0 = ks * 8;
            int ar = warp * 16 + gid;
            uint32_t a0 = __float_as_uint(Xs[ar * 36 + k0 + tig]);
            uint32_t a1 = __float_as_uint(Xs[(ar + 8) * 36 + k0 + tig]);
            uint32_t a2 = __float_as_uint(Xs[ar * 36 + k0 + tig + 4]);
            uint32_t a3 = __float_as_uint(Xs[(ar + 8) * 36 + k0 + tig + 4]);
#pragma unroll
            for (int nt = 0; nt < 16; nt++) {
                int col = nt * 8 + gid;
                uint32_t b0 = __float_as_uint(Ws[(k0 + tig) * 136 + col]);
                uint32_t b1 = __float_as_uint(Ws[(k0 + tig + 4) * 136 + col]);
                asm volatile(
                    "mma.sync.aligned.m16n8k8.row.col.f32.tf32.tf32.f32 "
                    "{%0,%1,%2,%3}, {%4,%5,%6,%7}, {%8,%9}, {%0,%1,%2,%3};"
                    : "+f"(acc[nt][0]), "+f"(acc[nt][1]), "+f"(acc[nt][2]), "+f"(acc[nt][3])
                    : "r"(a0), "r"(a1), "r"(a2), "r"(a3), "r"(b0), "r"(b1));
            }
        }
    }

    // store: c0,c1 -> row=warp*16+gid, cols nt*8 + 2*tig (+1); c2,c3 -> row+8
    int r_lo = row0 + warp * 16 + gid;
    int r_hi = r_lo + 8;
#pragma unroll
    for (int nt = 0; nt < 16; nt++) {
        int c = nt * 8 + 2 * tig;
        if (r_lo < N)
            *reinterpret_cast<float2*>(g_xw + (size_t)r_lo * F + c) =
                make_float2(acc[nt][0], acc[nt][1]);
        if (r_hi < N)
            *reinterpret_cast<float2*>(g_xw + (size_t)r_hi * F + c) =
                make_float2(acc[nt][2], acc[nt][3]);
    }
}

// ---------------------------------------------------------------------------
// 6) Fused aggregation + tanh + linear output. Warp per dst node.
//    Shfl-free: broadcast __ldg of packed edges, 4 independent gathers/iter.
// ---------------------------------------------------------------------------
__global__ void k_agg_out(const float* __restrict__ wlin,
                          const float* __restrict__ blin,
                          float* __restrict__ out, int N) {
    int node = (blockIdx.x * blockDim.x + threadIdx.x) >> 5;
    int lane = threadIdx.x & 31;
    if (node >= N) return;

    float di = g_dinv[node];
    float4 v0 = reinterpret_cast<const float4*>(g_xw + (size_t)node * F)[lane];
    float sc = di * di;
    float ax = sc * v0.x, ay = sc * v0.y, az = sc * v0.z, aw = sc * v0.w;

    int e = g_off[node];
    int end = e + g_cnt[node];

    for (; e + 4 <= end; e += 4) {
        int2 q0 = __ldg(g_edge + e);
        int2 q1 = __ldg(g_edge + e + 1);
        int2 q2 = __ldg(g_edge + e + 2);
        int2 q3 = __ldg(g_edge + e + 3);
        float4 a0 = __ldg(reinterpret_cast<const float4*>(g_xw + (size_t)q0.x * F) + lane);
        float4 a1 = __ldg(reinterpret_cast<const float4*>(g_xw + (size_t)q1.x * F) + lane);
        float4 a2 = __ldg(reinterpret_cast<const float4*>(g_xw + (size_t)q2.x * F) + lane);
        float4 a3 = __ldg(reinterpret_cast<const float4*>(g_xw + (size_t)q3.x * F) + lane);
        float c0 = __int_as_float(q0.y), c1 = __int_as_float(q1.y);
        float c2 = __int_as_float(q2.y), c3 = __int_as_float(q3.y);
        ax += c0 * a0.x + c1 * a1.x + c2 * a2.x + c3 * a3.x;
        ay += c0 * a0.y + c1 * a1.y + c2 * a2.y + c3 * a3.y;
        az += c0 * a0.z + c1 * a1.z + c2 * a2.z + c3 * a3.z;
        aw += c0 * a0.w + c1 * a1.w + c2 * a2.w + c3 * a3.w;
    }
    for (; e < end; e++) {
        int2 q = __ldg(g_edge + e);
        float4 a = __ldg(reinterpret_cast<const float4*>(g_xw + (size_t)q.x * F) + lane);
        float c = __int_as_float(q.y);
        ax += c * a.x; ay += c * a.y; az += c * a.z; aw += c * a.w;
    }

    float4 wv = reinterpret_cast<const float4*>(wlin)[lane];
    float sum = tanhf(ax) * wv.x + tanhf(ay) * wv.y +
                tanhf(az) * wv.z + tanhf(aw) * wv.w;
#pragma unroll
    for (int o = 16; o; o >>= 1) sum += __shfl_xor_sync(0xffffffffu, sum, o);
    if (lane == 0) out[node] = sum + __ldg(blin);
}

// ---------------------------------------------------------------------------
extern "C" void kernel_launch(void* const* d_in, const int* in_sizes, int n_in,
                              void* d_out, int out_size) {
    const float* x    = (const float*)d_in[0];
    const int*   ei   = (const int*)d_in[1];
    const float* ew   = (const float*)d_in[2];
    const float* W0   = (const float*)d_in[3];
    const float* Wih  = (const float*)d_in[4];
    const float* Whh  = (const float*)d_in[5];
    const float* bih  = (const float*)d_in[6];
    const float* bhh  = (const float*)d_in[7];
    const float* wlin = (const float*)d_in[8];
    const float* blin = (const float*)d_in[9];
    float* out = (float*)d_out;

    int N = in_sizes[0] / F;
    int E = in_sizes[2];
    const int* src = ei;
    const int* dst = ei + E;
    int nb = (N + 255) / 256;

    k_gru_zero<<<nb, 256>>>(W0, Wih, Whh, bih, bhh, N);
    k_hist<<<(E + 255) / 256, 256>>>(dst, ew, E);
    k_scan1_dinv<<<nb, 256>>>(N);
    k_scan2<<<1, 256>>>(nb);
    k_scan3<<<nb, 256>>>(N);
    k_place<<<(E + 255) / 256, 256>>>(src, dst, ew, E);
    k_gemm_tc<<<(N + 127) / 128, 256>>>(x, N);
    k_agg_out<<<(N + 7) / 8, 256>>>(wlin, blin, out, N);
}

// round 11
// speedup vs baseline: 1.5130x; 1.0106x over previous
#include <cuda_runtime.h>
#include <math.h>
#include <stdint.h>

#define F 128
#define MAXN 50048
#define MAXE 800064

// Scratch (__device__ globals; no allocation allowed)
__device__ __align__(16) float g_W[F * F];              // evolved weight
__device__ __align__(16) float g_xw[(size_t)MAXN * F];  // x @ W (fp32)
__device__ float g_dinv[MAXN];                          // deg -> rsqrt(deg)
__device__ int   g_cnt[MAXN];                           // per-dst edge count
__device__ int   g_off[MAXN];                           // exclusive scan
__device__ int   g_cur[MAXN];                           // placement cursors
__device__ unsigned g_scanstate[256];                   // lookback status
__device__ __align__(16) int2 g_edge[MAXE];             // dst-sorted (src, coef)

__device__ __forceinline__ uint32_t f2tf32(float f) {
    uint32_t u;
    asm("cvt.rna.tf32.f32 %0, %1;" : "=r"(u) : "f"(f));
    return u;
}

// ---------------------------------------------------------------------------
// 1) GRU weight evolution fused with counter/state init.
// ---------------------------------------------------------------------------
__global__ void k_gru_zero(const float* __restrict__ W0,
                           const float* __restrict__ Wih,
                           const float* __restrict__ Whh,
                           const float* __restrict__ bih,
                           const float* __restrict__ bhh, int N) {
    int t = blockIdx.x * blockDim.x + threadIdx.x;
    if (t < N) { g_cnt[t] = 0; g_dinv[t] = 1.0f; }   // self-loop weight = 1
    if (t < 256) g_scanstate[t] = 0;                  // reset lookback state
    if (t >= F * F) return;
    int i = t >> 7;
    int j = t & 127;

    const float* w0r = W0 + i * F;
    const float* a_r = Wih + (size_t)j * F;
    const float* a_z = Wih + (size_t)(j + F) * F;
    const float* a_n = Wih + (size_t)(j + 2 * F) * F;
    const float* h_r = Whh + (size_t)j * F;
    const float* h_z = Whh + (size_t)(j + F) * F;
    const float* h_n = Whh + (size_t)(j + 2 * F) * F;

    float ir = 0.f, iz = 0.f, in_ = 0.f, hr = 0.f, hz = 0.f, hn = 0.f;
#pragma unroll 8
    for (int k = 0; k < F; k++) {
        float w0 = __ldg(w0r + k);
        ir += w0 * __ldg(a_r + k);
        iz += w0 * __ldg(a_z + k);
        in_ += w0 * __ldg(a_n + k);
        hr += w0 * __ldg(h_r + k);
        hz += w0 * __ldg(h_z + k);
        hn += w0 * __ldg(h_n + k);
    }
    ir += __ldg(bih + j);
    iz += __ldg(bih + j + F);
    in_ += __ldg(bih + j + 2 * F);
    hr += __ldg(bhh + j);
    hz += __ldg(bhh + j + F);
    hn += __ldg(bhh + j + 2 * F);

    float r = 1.f / (1.f + expf(-(ir + hr)));
    float z = 1.f / (1.f + expf(-(iz + hz)));
    float n = tanhf(in_ + r * hn);
    g_W[t] = (1.f - z) * n + z * __ldg(W0 + t);
}

// ---------------------------------------------------------------------------
// 2) histogram (2 edges/thread): per-dst count + weighted degree
// ---------------------------------------------------------------------------
__global__ void k_hist(const int* __restrict__ dst,
                       const float* __restrict__ ew, int E) {
    int t = blockIdx.x * blockDim.x + threadIdx.x;
    int e0 = t * 2;
    if (e0 + 1 < E) {
        int2 dd = __ldg(reinterpret_cast<const int2*>(dst) + t);
        float2 ww = __ldg(reinterpret_cast<const float2*>(ew) + t);
        atomicAdd(&g_cnt[dd.x], 1);
        atomicAdd(&g_dinv[dd.x], ww.x);
        atomicAdd(&g_cnt[dd.y], 1);
        atomicAdd(&g_dinv[dd.y], ww.y);
    } else if (e0 < E) {
        int d = __ldg(dst + e0);
        atomicAdd(&g_cnt[d], 1);
        atomicAdd(&g_dinv[d], __ldg(ew + e0));
    }
}

// ---------------------------------------------------------------------------
// 3) Single-pass scan (decoupled lookback) + dinv finalize + cursor init.
// ---------------------------------------------------------------------------
__global__ void k_scan(int N) {
    __shared__ int sh[256];
    __shared__ int s_prev;
    int tid = threadIdx.x;
    int gid = blockIdx.x * 256 + tid;

    if (gid < N) {  // dinv finalize (hist complete)
        float d = g_dinv[gid];
        g_dinv[gid] = (d > 0.f) ? rsqrtf(d) : 0.f;
    }
    int v = (gid < N) ? g_cnt[gid] : 0;
    sh[tid] = v;
    __syncthreads();
#pragma unroll
    for (int o = 1; o < 256; o <<= 1) {
        int t = (tid >= o) ? sh[tid - o] : 0;
        __syncthreads();
        sh[tid] += t;
        __syncthreads();
    }
    int total = sh[255];

    if (tid == 0) {
        int prev = 0;
        if (blockIdx.x == 0) {
            atomicExch(&g_scanstate[0], (2u << 30) | (unsigned)total);
        } else {
            atomicExch(&g_scanstate[blockIdx.x], (1u << 30) | (unsigned)total);
            int b = blockIdx.x - 1;
            while (true) {
                unsigned s = atomicAdd(&g_scanstate[b], 0u);
                unsigned st = s >> 30;
                if (st == 0u) continue;                 // not published yet
                prev += (int)(s & 0x3FFFFFFFu);
                if (st == 2u) break;                    // full prefix known
                b--;
            }
            atomicExch(&g_scanstate[blockIdx.x],
                       (2u << 30) | (unsigned)(prev + total));
        }
        s_prev = prev;
    }
    __syncthreads();
    if (gid < N) {
        int off = s_prev + sh[tid] - v;   // exclusive
        g_off[gid] = off;
        g_cur[gid] = off;
    }
}

// ---------------------------------------------------------------------------
// 4) FUSED placement + tensor-core GEMM (independent; branch on blockIdx).
// ---------------------------------------------------------------------------
__global__ void __launch_bounds__(256) k_place_gemm(
        const int* __restrict__ src, const int* __restrict__ dst,
        const float* __restrict__ ew, int E,
        const float* __restrict__ x, int N, int gemmBlocks) {

    if ((int)blockIdx.x >= gemmBlocks) {
        // ---------------- placement: 2 edges/thread ----------------
        int t = (blockIdx.x - gemmBlocks) * blockDim.x + threadIdx.x;
        int e0 = t * 2;
        if (e0 + 1 < E) {
            int2 ss = __ldg(reinterpret_cast<const int2*>(src) + t);
            int2 dd = __ldg(reinterpret_cast<const int2*>(dst) + t);
            float2 ww = __ldg(reinterpret_cast<const float2*>(ew) + t);
            float c0 = g_dinv[ss.x] * ww.x * g_dinv[dd.x];
            float c1 = g_dinv[ss.y] * ww.y * g_dinv[dd.y];
            int p0 = atomicAdd(&g_cur[dd.x], 1);
            g_edge[p0] = make_int2(ss.x, __float_as_int(c0));
            int p1 = atomicAdd(&g_cur[dd.y], 1);
            g_edge[p1] = make_int2(ss.y, __float_as_int(c1));
        } else if (e0 < E) {
            int s = __ldg(src + e0);
            int d = __ldg(dst + e0);
            float c = g_dinv[s] * __ldg(ew + e0) * g_dinv[d];
            int p = atomicAdd(&g_cur[d], 1);
            g_edge[p] = make_int2(s, __float_as_int(c));
        }
        return;
    }

    // ---------------- GEMM: g_xw = x @ g_W (tf32 mma, fp32 accum) ---------
    __shared__ float Xs[128 * 36];
    __shared__ float Ws[32 * 136];
    int tid = threadIdx.x;
    int warp = tid >> 5, lane = tid & 31;
    int row0 = blockIdx.x * 128;
    int gid = lane >> 2;
    int tig = lane & 3;

    float acc[16][4];
#pragma unroll
    for (int nt = 0; nt < 16; nt++)
#pragma unroll
        for (int c = 0; c < 4; c++) acc[nt][c] = 0.f;

    for (int kt = 0; kt < 4; kt++) {
        __syncthreads();
#pragma unroll
        for (int i = 0; i < 4; i++) {
            int e = tid + i * 256;
            int r = e >> 3, kg = e & 7;
            float4 v = make_float4(0.f, 0.f, 0.f, 0.f);
            if (row0 + r < N)
                v = __ldg(reinterpret_cast<const float4*>(x + (size_t)(row0 + r) * F + kt * 32) + kg);
            v.x = __uint_as_float(f2tf32(v.x));
            v.y = __uint_as_float(f2tf32(v.y));
            v.z = __uint_as_float(f2tf32(v.z));
            v.w = __uint_as_float(f2tf32(v.w));
            reinterpret_cast<float4*>(Xs)[r * 9 + kg] = v;
        }
#pragma unroll
        for (int i = 0; i < 4; i++) {
            int e = tid + i * 256;
            int r = e >> 5, cg = e & 31;
            float4 v = reinterpret_cast<const float4*>(g_W + (size_t)(kt * 32 + r) * F)[cg];
            v.x = __uint_as_float(f2tf32(v.x));
            v.y = __uint_as_float(f2tf32(v.y));
            v.z = __uint_as_float(f2tf32(v.z));
            v.w = __uint_as_float(f2tf32(v.w));
            reinterpret_cast<float4*>(Ws)[r * 34 + cg] = v;
        }
        __syncthreads();

#pragma unroll
        for (int ks = 0; ks < 4; ks++) {
            int k0 = ks * 8;
            int ar = warp * 16 + gid;
            uint32_t a0 = __float_as_uint(Xs[ar * 36 + k0 + tig]);
            uint32_t a1 = __float_as_uint(Xs[(ar + 8) * 36 + k0 + tig]);
            uint32_t a2 = __float_as_uint(Xs[ar * 36 + k0 + tig + 4]);
            uint32_t a3 = __float_as_uint(Xs[(ar + 8) * 36 + k0 + tig + 4]);
#pragma unroll
            for (int nt = 0; nt < 16; nt++) {
                int col = nt * 8 + gid;
                uint32_t b0 = __float_as_uint(Ws[(k0 + tig) * 136 + col]);
                uint32_t b1 = __float_as_uint(Ws[(k0 + tig + 4) * 136 + col]);
                asm volatile(
                    "mma.sync.aligned.m16n8k8.row.col.f32.tf32.tf32.f32 "
                    "{%0,%1,%2,%3}, {%4,%5,%6,%7}, {%8,%9}, {%0,%1,%2,%3};"
                    : "+f"(acc[nt][0]), "+f"(acc[nt][1]), "+f"(acc[nt][2]), "+f"(acc[nt][3])
                    : "r"(a0), "r"(a1), "r"(a2), "r"(a3), "r"(b0), "r"(b1));
            }
        }
    }

    int r_lo = row0 + warp * 16 + gid;
    int r_hi = r_lo + 8;
#pragma unroll
    for (int nt = 0; nt < 16; nt++) {
        int c = nt * 8 + 2 * tig;
        if (r_lo < N)
            *reinterpret_cast<float2*>(g_xw + (size_t)r_lo * F + c) =
                make_float2(acc[nt][0], acc[nt][1]);
        if (r_hi < N)
            *reinterpret_cast<float2*>(g_xw + (size_t)r_hi * F + c) =
                make_float2(acc[nt][2], acc[nt][3]);
    }
}

// ---------------------------------------------------------------------------
// 5) Fused aggregation + tanh + linear output. Warp per dst node.
//    fp32 float4 gathers (bf16 variant exceeded error budget — reverted).
// ---------------------------------------------------------------------------
__global__ void k_agg_out(const float* __restrict__ wlin,
                          const float* __restrict__ blin,
                          float* __restrict__ out, int N) {
    int node = (blockIdx.x * blockDim.x + threadIdx.x) >> 5;
    int lane = threadIdx.x & 31;
    if (node >= N) return;

    float di = g_dinv[node];
    float4 v0 = reinterpret_cast<const float4*>(g_xw + (size_t)node * F)[lane];
    float sc = di * di;
    float ax = sc * v0.x, ay = sc * v0.y, az = sc * v0.z, aw = sc * v0.w;

    int e = g_off[node];
    int end = e + g_cnt[node];

    for (; e + 4 <= end; e += 4) {
        int2 q0 = __ldg(g_edge + e);
        int2 q1 = __ldg(g_edge + e + 1);
        int2 q2 = __ldg(g_edge + e + 2);
        int2 q3 = __ldg(g_edge + e + 3);
        float4 a0 = __ldg(reinterpret_cast<const float4*>(g_xw + (size_t)q0.x * F) + lane);
        float4 a1 = __ldg(reinterpret_cast<const float4*>(g_xw + (size_t)q1.x * F) + lane);
        float4 a2 = __ldg(reinterpret_cast<const float4*>(g_xw + (size_t)q2.x * F) + lane);
        float4 a3 = __ldg(reinterpret_cast<const float4*>(g_xw + (size_t)q3.x * F) + lane);
        float c0 = __int_as_float(q0.y), c1 = __int_as_float(q1.y);
        float c2 = __int_as_float(q2.y), c3 = __int_as_float(q3.y);
        ax += c0 * a0.x + c1 * a1.x + c2 * a2.x + c3 * a3.x;
        ay += c0 * a0.y + c1 * a1.y + c2 * a2.y + c3 * a3.y;
        az += c0 * a0.z + c1 * a1.z + c2 * a2.z + c3 * a3.z;
        aw += c0 * a0.w + c1 * a1.w + c2 * a2.w + c3 * a3.w;
    }
    for (; e < end; e++) {
        int2 q = __ldg(g_edge + e);
        float4 a = __ldg(reinterpret_cast<const float4*>(g_xw + (size_t)q.x * F) + lane);
        float c = __int_as_float(q.y);
        ax += c * a.x; ay += c * a.y; az += c * a.z; aw += c * a.w;
    }

    float4 wv = reinterpret_cast<const float4*>(wlin)[lane];
    float sum = tanhf(ax) * wv.x + tanhf(ay) * wv.y +
                tanhf(az) * wv.z + tanhf(aw) * wv.w;
#pragma unroll
    for (int o = 16; o; o >>= 1) sum += __shfl_xor_sync(0xffffffffu, sum, o);
    if (lane == 0) out[node] = sum + __ldg(blin);
}

// ---------------------------------------------------------------------------
extern "C" void kernel_launch(void* const* d_in, const int* in_sizes, int n_in,
                              void* d_out, int out_size) {
    const float* x    = (const float*)d_in[0];
    const int*   ei   = (const int*)d_in[1];
    const float* ew   = (const float*)d_in[2];
    const float* W0   = (const float*)d_in[3];
    const float* Wih  = (const float*)d_in[4];
    const float* Whh  = (const float*)d_in[5];
    const float* bih  = (const float*)d_in[6];
    const float* bhh  = (const float*)d_in[7];
    const float* wlin = (const float*)d_in[8];
    const float* blin = (const float*)d_in[9];
    float* out = (float*)d_out;

    int N = in_sizes[0] / F;
    int E = in_sizes[2];
    const int* src = ei;
    const int* dst = ei + E;
    int nb = (N + 255) / 256;                       // 196 for N=50000 (<=256)
    int gemmBlocks = (N + 127) / 128;
    int placeBlocks = (E + 511) / 512;              // 2 edges/thread

    k_gru_zero<<<nb, 256>>>(W0, Wih, Whh, bih, bhh, N);
    k_hist<<<(E + 511) / 512, 256>>>(dst, ew, E);
    k_scan<<<nb, 256>>>(N);
    k_place_gemm<<<gemmBlocks + placeBlocks, 256>>>(src, dst, ew, E, x, N, gemmBlocks);
    k_agg_out<<<(N + 7) / 8, 256>>>(wlin, blin, out, N);
}